// round 16
// baseline (speedup 1.0000x reference)
#include <cuda_runtime.h>
#include <math.h>
#include <stdint.h>

#define Bc 16
#define Lc 2048
#define Dc 192
#define Hc 4
#define Kc 12

// ---------------- scratch (no allocations allowed) ----------------
__device__ float g_xn [(size_t)Bc*Lc*Dc];       // xn2 (written by fused proj+LN2)
__device__ float g_q  [(size_t)Bc*Hc*Lc*Kc];    // [B,H,L,K]
__device__ float g_k  [(size_t)Bc*Hc*Lc*Kc];
__device__ float g_v  [(size_t)Bc*Hc*Lc*Kc];
__device__ float g_ctx[(size_t)Bc*Lc*Hc*Kc];    // [B,L,H,K]
__device__ float g_y1 [(size_t)Bc*Lc*Dc];       // x + MHA
__device__ float g_h  [(size_t)Bc*Lc*Dc];       // relu(conv1), zero rows 0, L-1

__device__ __forceinline__ float ex2(float x) {
    float y; asm("ex2.approx.f32 %0, %1;" : "=f"(y) : "f"(x)); return y;
}
__device__ __forceinline__ float to_tf32(float x) {
    uint32_t u; asm("cvt.rna.tf32.f32 %0, %1;" : "=r"(u) : "f"(x));
    return __uint_as_float(u);
}
__device__ __forceinline__ uint32_t tf32b(float x) {
    uint32_t u; asm("cvt.rna.tf32.f32 %0, %1;" : "=r"(u) : "f"(x));
    return u;
}
// RNA-round a float4 in registers, then one STS.128 at the call site.
__device__ __forceinline__ float4 tf32x4(float4 v) {
    return make_float4(to_tf32(v.x), to_tf32(v.y), to_tf32(v.z), to_tf32(v.w));
}
__device__ __forceinline__ void mma_tf32(float* c, const uint32_t* a,
                                         uint32_t b0, uint32_t b1)
{
    asm volatile(
        "mma.sync.aligned.m16n8k8.row.col.f32.tf32.tf32.f32 "
        "{%0,%1,%2,%3}, {%4,%5,%6,%7}, {%8,%9}, {%0,%1,%2,%3};"
        : "+f"(c[0]), "+f"(c[1]), "+f"(c[2]), "+f"(c[3])
        : "r"(a[0]), "r"(a[1]), "r"(a[2]), "r"(a[3]), "r"(b0), "r"(b1));
}

// ---------------- QKV projection + fused LN1: tf32 MMA ----------------
// M=64/block, N=3x48, K=192. 192 threads = 6 warps.
#define QA_S 196
#define QB_S 152
#define QA_FLOATS (64 * QA_S)
#define QB_FLOATS (32 * QB_S)
#define QKV_SMEM_BYTES ((QA_FLOATS + 2 * QB_FLOATS) * 4)

__global__ __launch_bounds__(192, 2)
void qkv_mma_kernel(const float* __restrict__ x,
                    const float* __restrict__ ln_g, const float* __restrict__ ln_b,
                    const float* __restrict__ wq, const float* __restrict__ bq,
                    const float* __restrict__ wk, const float* __restrict__ bk,
                    const float* __restrict__ wv, const float* __restrict__ bv)
{
    extern __shared__ float smem[];
    float* sA = smem;                 // [64][196] raw x rows -> LN'd tf32 in-place
    float* sB = smem + QA_FLOATS;     // [2][32][152] tf32 weights (q|k|v cols)

    const int tid  = threadIdx.x;
    const int w    = tid >> 5;
    const int lane = tid & 31;
    const int tig  = lane & 3;
    const int grp  = lane >> 2;
    const int rowbase = blockIdx.x * 64;
    const int bb   = rowbase / Lc;
    const int lloc = rowbase % Lc;

    auto loadW = [&](int kc, int bf) {
        float* dstb = sB + bf * QB_FLOATS;
#pragma unroll
        for (int it = 0; it < 6; it++) {
            int idx = tid + it * 192;            // 32*36 float4 = 1152
            int k = idx / 36, c = (idx % 36) * 4;
            int m = c / 48, lc = c % 48;
            const float* src = (m == 0) ? wq : (m == 1) ? wk : wv;
            float4 v = *(const float4*)(src + (size_t)(kc * 32 + k) * 48 + lc);
            *(float4*)(dstb + k * QB_S + c) = tf32x4(v);
        }
    };

    for (int idx = tid; idx < 64 * 48; idx += 192) {
        int r = idx / 48, c4 = (idx % 48) * 4;
        *(float4*)(sA + r * QA_S + c4) =
            *(const float4*)(x + (size_t)(rowbase + r) * Dc + c4);
    }
    loadW(0, 0);
    __syncthreads();

    // fused LN1: warp w handles rows w, w+6, ...
    for (int r = w; r < 64; r += 6) {
        float vv[6]; float s = 0.f;
#pragma unroll
        for (int i = 0; i < 6; i++) { vv[i] = sA[r * QA_S + lane + 32*i]; s += vv[i]; }
#pragma unroll
        for (int o = 16; o; o >>= 1) s += __shfl_xor_sync(0xffffffffu, s, o);
        float mean = s * (1.f/192.f);
        float vs = 0.f;
#pragma unroll
        for (int i = 0; i < 6; i++) { float dd = vv[i] - mean; vs += dd*dd; }
#pragma unroll
        for (int o = 16; o; o >>= 1) vs += __shfl_xor_sync(0xffffffffu, vs, o);
        float inv = rsqrtf(vs * (1.f/192.f) + 1e-3f);
#pragma unroll
        for (int i = 0; i < 6; i++) {
            int c = lane + 32*i;
            sA[r * QA_S + c] = to_tf32((vv[i] - mean) * inv * ln_g[c] + ln_b[c]);
        }
    }
    __syncthreads();

    const int s     = w >> 1;
    const int mbase = (w & 1) * 32;
    float c[2][6][4];
#pragma unroll
    for (int i = 0; i < 2; i++)
#pragma unroll
        for (int j = 0; j < 6; j++)
#pragma unroll
            for (int q = 0; q < 4; q++) c[i][j][q] = 0.f;

    int buf = 0;
    for (int kc = 0; kc < 6; kc++) {
        if (kc < 5) loadW(kc + 1, buf ^ 1);
        const float* bBuf = sB + buf * QB_FLOATS + s * 48;
#pragma unroll
        for (int ks = 0; ks < 4; ks++) {
            const int c0 = kc * 32 + ks * 8;
            uint32_t a[2][4];
#pragma unroll
            for (int mt = 0; mt < 2; mt++) {
                const float* ap = sA + (mbase + mt * 16 + grp) * QA_S + c0 + tig;
                a[mt][0] = __float_as_uint(ap[0]);
                a[mt][1] = __float_as_uint(ap[8 * QA_S]);
                a[mt][2] = __float_as_uint(ap[4]);
                a[mt][3] = __float_as_uint(ap[8 * QA_S + 4]);
            }
            const float* bp = bBuf + (ks * 8 + tig) * QB_S + grp;
#pragma unroll
            for (int nt = 0; nt < 6; nt++) {
                uint32_t b0 = __float_as_uint(bp[nt * 8]);
                uint32_t b1 = __float_as_uint(bp[nt * 8 + 4 * QB_S]);
                mma_tf32(c[0][nt], a[0], b0, b1);
                mma_tf32(c[1][nt], a[1], b0, b1);
            }
        }
        __syncthreads();
        buf ^= 1;
    }

    const float* Bp = (s == 0) ? bq : (s == 1) ? bk : bv;
    float* O = (s == 0) ? g_q : (s == 1) ? g_k : g_v;
#pragma unroll
    for (int mt = 0; mt < 2; mt++) {
#pragma unroll
        for (int rs = 0; rs < 2; rs++) {
            int l = lloc + mbase + mt * 16 + grp + rs * 8;
#pragma unroll
            for (int nt = 0; nt < 6; nt++) {
                int n = nt * 8 + tig * 2;       // 0..47, even
                int h = n / 12, kk = n % 12;
                float2 res;
                res.x = c[mt][nt][rs * 2 + 0] + Bp[n];
                res.y = c[mt][nt][rs * 2 + 1] + Bp[n + 1];
                *(float2*)(O + (((size_t)bb * Hc + h) * Lc + l) * Kc + kk) = res;
            }
        }
    }
}

// ---------------- causal attention: tf32 MMA flash (no-max softmax) -----------
// Block: 128 queries (8 warps x 16 rows), 64-key tiles.
#define SK_S 20
#define SV_S 68
#define SP_S 68

__global__ __launch_bounds__(256)
void attn_kernel()
{
    __shared__ float sK[64][SK_S];      // [key][dim0..15] tf32 (12..15 zero)
    __shared__ float sVt[16][SV_S];     // [dim0..15][key] tf32 (rows 12..15 zero)
    __shared__ float sP[8][16][SP_S];   // per-warp P slice [qrow][key] tf32

    const int qt   = gridDim.x - 1 - blockIdx.x;   // heavy tiles first
    const int h    = blockIdx.y, bb = blockIdx.z;
    const int tid  = threadIdx.x;
    const int w    = tid >> 5;
    const int lane = tid & 31;
    const int grp  = lane >> 2;
    const int tig  = lane & 3;

    size_t head = ((size_t)bb * Hc + h) * Lc * Kc;
    const float* qp = g_q + head;
    const float* kp = g_k + head;
    const float* vp = g_v + head;

    // zero pad regions (written once; first-tile __syncthreads publishes)
    sK[tid >> 2][12 + (tid & 3)] = 0.f;             // 256 threads = 64x4
    sVt[12 + (tid >> 6)][tid & 63] = 0.f;           // 256 threads = 4x64

    const int qbase = qt * 128;
    const int l0 = qbase + w * 16 + grp;
    const int l8 = l0 + 8;
    const float scale = 0.4164682333693345f;        // log2(e)/sqrt(12)

    // Q fragments (2 k-chunks), scaled, tf32 (RNA)
    uint32_t qa[2][4];
    qa[0][0] = tf32b(qp[(size_t)l0 * 12 + tig] * scale);
    qa[0][1] = tf32b(qp[(size_t)l8 * 12 + tig] * scale);
    qa[0][2] = tf32b(qp[(size_t)l0 * 12 + tig + 4] * scale);
    qa[0][3] = tf32b(qp[(size_t)l8 * 12 + tig + 4] * scale);
    qa[1][0] = tf32b(qp[(size_t)l0 * 12 + tig + 8] * scale);
    qa[1][1] = tf32b(qp[(size_t)l8 * 12 + tig + 8] * scale);
    qa[1][2] = 0u;
    qa[1][3] = 0u;

    float oc[2][4];
#pragma unroll
    for (int i = 0; i < 2; i++)
#pragma unroll
        for (int j = 0; j < 4; j++) oc[i][j] = 0.f;
    float dsum0 = 0.f, dsum1 = 0.f;

    const int qloc0 = w * 16 + grp;
    const int qloc1 = qloc0 + 8;
    const int ntile = 2 * qt + 2;

    for (int kt = 0; kt < ntile; kt++) {
        __syncthreads();
        // stage K (cvt in regs -> STS.128) and V transposed (scalar cvt)
        {
            int i = tid;                            // 192 active
            if (i < 192) {
                int key = i / 3, c4 = (i % 3) * 4;
                float4 kv = *(const float4*)(kp + (size_t)(kt * 64 + key) * 12 + c4);
                *(float4*)&sK[key][c4] = tf32x4(kv);
                float4 vv = *(const float4*)(vp + (size_t)(kt * 64 + key) * 12 + c4);
                sVt[c4+0][key] = to_tf32(vv.x); sVt[c4+1][key] = to_tf32(vv.y);
                sVt[c4+2][key] = to_tf32(vv.z); sVt[c4+3][key] = to_tf32(vv.w);
            }
        }
        __syncthreads();

        // scores: c[nt] = Q(16 rows) @ K^T(8 keys per nt)
        float c[8][4];
#pragma unroll
        for (int nt = 0; nt < 8; nt++) {
            c[nt][0] = 0.f; c[nt][1] = 0.f; c[nt][2] = 0.f; c[nt][3] = 0.f;
        }
#pragma unroll
        for (int nt = 0; nt < 8; nt++) {
#pragma unroll
            for (int kc = 0; kc < 2; kc++) {
                uint32_t b0 = __float_as_uint(sK[nt * 8 + grp][kc * 8 + tig]);
                uint32_t b1 = __float_as_uint(sK[nt * 8 + grp][kc * 8 + tig + 4]);
                mma_tf32(c[nt], qa[kc], b0, b1);
            }
        }

        // softmax (no-max): p = 2^s, causal mask on diagonal tiles
        const bool masked = (kt >= 2 * qt);
        const int koff = (kt - 2 * qt) * 64;
#pragma unroll
        for (int nt = 0; nt < 8; nt++) {
            int kl = nt * 8 + 2 * tig;
            float p0 = ex2(c[nt][0]);
            float p1 = ex2(c[nt][1]);
            float p2 = ex2(c[nt][2]);
            float p3 = ex2(c[nt][3]);
            if (masked) {
                if (koff + kl     > qloc0) p0 = 0.f;
                if (koff + kl + 1 > qloc0) p1 = 0.f;
                if (koff + kl     > qloc1) p2 = 0.f;
                if (koff + kl + 1 > qloc1) p3 = 0.f;
            }
            dsum0 += p0 + p1;
            dsum1 += p2 + p3;
            float2 lo = make_float2(to_tf32(p0), to_tf32(p1));
            float2 hi = make_float2(to_tf32(p2), to_tf32(p3));
            *(float2*)&sP[w][grp]    [kl] = lo;
            *(float2*)&sP[w][grp + 8][kl] = hi;
        }
        __syncwarp();

        // PV: oc += P(16 rows x 64 keys) @ V(64 keys x 16 dims)
#pragma unroll
        for (int kc = 0; kc < 8; kc++) {
            uint32_t a[4];
            a[0] = __float_as_uint(sP[w][grp]    [kc * 8 + tig]);
            a[1] = __float_as_uint(sP[w][grp + 8][kc * 8 + tig]);
            a[2] = __float_as_uint(sP[w][grp]    [kc * 8 + tig + 4]);
            a[3] = __float_as_uint(sP[w][grp + 8][kc * 8 + tig + 4]);
#pragma unroll
            for (int nt2 = 0; nt2 < 2; nt2++) {
                uint32_t b0 = __float_as_uint(sVt[nt2 * 8 + grp][kc * 8 + tig]);
                uint32_t b1 = __float_as_uint(sVt[nt2 * 8 + grp][kc * 8 + tig + 4]);
                mma_tf32(oc[nt2], a, b0, b1);
            }
        }
    }

    // reduce row sums across the 4 tig lanes (same grp)
    dsum0 += __shfl_xor_sync(0xffffffffu, dsum0, 1);
    dsum0 += __shfl_xor_sync(0xffffffffu, dsum0, 2);
    dsum1 += __shfl_xor_sync(0xffffffffu, dsum1, 1);
    dsum1 += __shfl_xor_sync(0xffffffffu, dsum1, 2);
    float i0 = 1.f / dsum0, i1 = 1.f / dsum1;

    float* o0 = g_ctx + (((size_t)bb * Lc + l0) * Hc + h) * Kc;
    float* o1 = g_ctx + (((size_t)bb * Lc + l8) * Hc + h) * Kc;
    *(float2*)(o0 + 2 * tig) = make_float2(oc[0][0] * i0, oc[0][1] * i0);
    *(float2*)(o1 + 2 * tig) = make_float2(oc[0][2] * i1, oc[0][3] * i1);
    if (tig < 2) {
        *(float2*)(o0 + 8 + 2 * tig) = make_float2(oc[1][0] * i0, oc[1][1] * i0);
        *(float2*)(o1 + 8 + 2 * tig) = make_float2(oc[1][2] * i1, oc[1][3] * i1);
    }
}

// ---------------- output projection + residual + fused LN2: tf32 MMA ----------
#define PA_S 52
#define PB_S 200
#define PA_FLOATS (64 * PA_S)
#define PB_FLOATS (48 * PB_S)
#define PST_S 196
#define PROJ_SMEM_BYTES ((PA_FLOATS + PB_FLOATS) * 4)   // 12928 floats > 64*196

__global__ __launch_bounds__(256, 4)
void proj_mma_kernel(const float* __restrict__ x,
                     const float* __restrict__ wo,
                     const float* __restrict__ bo,
                     const float* __restrict__ ln_g,
                     const float* __restrict__ ln_b)
{
    extern __shared__ float smem[];
    float* sA = smem;                 // [64][52]  ctx rows, tf32
    float* sB = smem + PA_FLOATS;     // [48][200] wo, tf32

    const int tid  = threadIdx.x;
    const int w    = tid >> 5;
    const int lane = tid & 31;
    const int tig  = lane & 3;
    const int grp  = lane >> 2;
    const int rowbase = blockIdx.x * 64;

    for (int idx = tid; idx < 64 * 12; idx += 256) {
        int r = idx / 12, c4 = (idx % 12) * 4;
        float4 v = *(const float4*)(g_ctx + (size_t)(rowbase + r) * 48 + c4);
        *(float4*)(sA + r * PA_S + c4) = tf32x4(v);
    }
    for (int idx = tid; idx < 48 * 48; idx += 256) {
        int r = idx / 48, c4 = (idx % 48) * 4;
        float4 v = *(const float4*)(wo + (size_t)r * Dc + c4);
        *(float4*)(sB + r * PB_S + c4) = tf32x4(v);
    }
    __syncthreads();

    const int mbase = (w & 1) * 32;
    const int nbase = (w >> 1) * 48;
    float c[2][6][4];
#pragma unroll
    for (int i = 0; i < 2; i++)
#pragma unroll
        for (int j = 0; j < 6; j++)
#pragma unroll
            for (int q = 0; q < 4; q++) c[i][j][q] = 0.f;

#pragma unroll
    for (int ks = 0; ks < 6; ks++) {
        const int c0 = ks * 8;
        uint32_t a[2][4];
#pragma unroll
        for (int mt = 0; mt < 2; mt++) {
            const float* ap = sA + (mbase + mt * 16 + grp) * PA_S + c0 + tig;
            a[mt][0] = __float_as_uint(ap[0]);
            a[mt][1] = __float_as_uint(ap[8 * PA_S]);
            a[mt][2] = __float_as_uint(ap[4]);
            a[mt][3] = __float_as_uint(ap[8 * PA_S + 4]);
        }
        const float* bp = sB + (c0 + tig) * PB_S + nbase + grp;
#pragma unroll
        for (int nt = 0; nt < 6; nt++) {
            uint32_t b0 = __float_as_uint(bp[nt * 8]);
            uint32_t b1 = __float_as_uint(bp[nt * 8 + 4 * PB_S]);
            mma_tf32(c[0][nt], a[0], b0, b1);
            mma_tf32(c[1][nt], a[1], b0, b1);
        }
    }
    __syncthreads();                       // done with sA/sB; reuse as stage

    float* stage = smem;                   // [64][196]
#pragma unroll
    for (int mt = 0; mt < 2; mt++) {
#pragma unroll
        for (int rs = 0; rs < 2; rs++) {
            int r = mbase + mt * 16 + grp + rs * 8;
            size_t off = (size_t)(rowbase + r) * Dc;
#pragma unroll
            for (int nt = 0; nt < 6; nt++) {
                int n = nbase + nt * 8 + tig * 2;
                float2 xv = *(const float2*)(x + off + n);
                float2 res;
                res.x = c[mt][nt][rs * 2 + 0] + bo[n]     + xv.x;
                res.y = c[mt][nt][rs * 2 + 1] + bo[n + 1] + xv.y;
                *(float2*)(g_y1 + off + n) = res;
                *(float2*)(stage + r * PST_S + n) = res;
            }
        }
    }
    __syncthreads();

    // fused LN2: warp w handles rows w, w+8, ... -> g_xn (fp32)
    for (int r = w; r < 64; r += 8) {
        float vv[6]; float s = 0.f;
#pragma unroll
        for (int i = 0; i < 6; i++) { vv[i] = stage[r * PST_S + lane + 32*i]; s += vv[i]; }
#pragma unroll
        for (int o = 16; o; o >>= 1) s += __shfl_xor_sync(0xffffffffu, s, o);
        float mean = s * (1.f/192.f);
        float vs = 0.f;
#pragma unroll
        for (int i = 0; i < 6; i++) { float dd = vv[i] - mean; vs += dd*dd; }
#pragma unroll
        for (int o = 16; o; o >>= 1) vs += __shfl_xor_sync(0xffffffffu, vs, o);
        float inv = rsqrtf(vs * (1.f/192.f) + 1e-3f);
#pragma unroll
        for (int i = 0; i < 6; i++) {
            int cc = lane + 32*i;
            g_xn[(size_t)(rowbase + r) * Dc + cc] =
                (vv[i] - mean) * inv * ln_g[cc] + ln_b[cc];
        }
    }
}

// ---------------- conv1d as tf32 tensor-core GEMM ----------------
// 3 blocks/SM: sA [66][196] + single-buffered 16-row weight chunk [16][200]
// = 63 KB smem. Prefetch-by-occupancy (24 warps/SM) replaces double-buffering.
// K-accumulation order identical to the 2-buffer version (same k sequence).
#define SA_STRIDE 196
#define SB_STRIDE 200
#define SA_FLOATS (66 * SA_STRIDE)
#define SB16_FLOATS (16 * SB_STRIDE)
#define CONV_SMEM_BYTES ((SA_FLOATS + SB16_FLOATS) * 4)

template<int MODE>
__global__ __launch_bounds__(256, 3)
void conv_mma_kernel(const float* __restrict__ W,
                     const float* __restrict__ bias,
                     float* __restrict__ out)
{
    extern __shared__ float smem[];
    float* sA = smem;                    // [66][196]
    float* sB = smem + SA_FLOATS;        // [16][200] single buffer

    const int tid  = threadIdx.x;
    const int w    = tid >> 5;
    const int lane = tid & 31;
    const int tig  = lane & 3;
    const int grp  = lane >> 2;
    const int l0   = blockIdx.x * 64;
    const int bb   = blockIdx.y;
    const float* srcb = ((MODE == 0) ? g_xn : g_h) + (size_t)bb * Lc * Dc;

    for (int idx = tid; idx < 66 * 48; idx += 256) {
        int r = idx / 48, c4 = (idx % 48) * 4;
        int l = l0 - 1 + r; l = l < 0 ? 0 : (l > Lc - 1 ? Lc - 1 : l);
        float4 v = *(const float4*)(srcb + (size_t)l * Dc + c4);
        *(float4*)(sA + r * SA_STRIDE + c4) = tf32x4(v);
    }

    const int mbase = (w & 1) * 32;
    const int nbase = (w >> 1) * 48;
    float c[2][6][4];
#pragma unroll
    for (int i = 0; i < 2; i++)
#pragma unroll
        for (int j = 0; j < 6; j++)
#pragma unroll
            for (int q = 0; q < 4; q++) c[i][j][q] = 0.f;

    // stage one 16-row weight chunk (rows kc2*16 .. +16 of the 576-row W)
    auto loadW = [&](int kc2) {
#pragma unroll
        for (int it = 0; it < 3; it++) {
            int idx = tid + it * 256;            // 16*48 = 768 float4
            int k = idx / 48, c4 = (idx % 48) * 4;
            float4 v = *(const float4*)(W + ((size_t)(kc2 * 16 + k)) * Dc + c4);
            *(float4*)(sB + k * SB_STRIDE + c4) = tf32x4(v);
        }
    };

    loadW(0);
    __syncthreads();

    int t = 0, cc = 0;                            // tap, channel base
    for (int kc2 = 0; kc2 < 36; kc2++) {
#pragma unroll
        for (int ks = 0; ks < 2; ks++) {
            const int c0 = cc + ks * 8;
            uint32_t a[2][4];
#pragma unroll
            for (int mt = 0; mt < 2; mt++) {
                const float* ap = sA + (mbase + mt * 16 + grp + t) * SA_STRIDE + c0 + tig;
                a[mt][0] = __float_as_uint(ap[0]);
                a[mt][1] = __float_as_uint(ap[8 * SA_STRIDE]);
                a[mt][2] = __float_as_uint(ap[4]);
                a[mt][3] = __float_as_uint(ap[8 * SA_STRIDE + 4]);
            }
            const float* bp = sB + (ks * 8 + tig) * SB_STRIDE + nbase + grp;
#pragma unroll
            for (int nt = 0; nt < 6; nt++) {
                uint32_t b0 = __float_as_uint(bp[nt * 8]);
                uint32_t b1 = __float_as_uint(bp[nt * 8 + 4 * SB_STRIDE]);
                mma_tf32(c[0][nt], a[0], b0, b1);
                mma_tf32(c[1][nt], a[1], b0, b1);
            }
        }
        __syncthreads();                          // chunk consumed
        if (kc2 < 35) {
            loadW(kc2 + 1);
            __syncthreads();                      // chunk ready
        }
        cc += 16;
        if (cc == 192) { cc = 0; t++; }
    }

    float* dst = (MODE == 0) ? g_h : out;
#pragma unroll
    for (int mt = 0; mt < 2; mt++) {
#pragma unroll
        for (int rs = 0; rs < 2; rs++) {
            int l = l0 + mbase + mt * 16 + grp + rs * 8;
            bool interior = (l >= 1) && (l <= Lc - 2);
            size_t rowoff = ((size_t)bb * Lc + l) * Dc;
#pragma unroll
            for (int nt = 0; nt < 6; nt++) {
                int n = nbase + nt * 8 + tig * 2;
                float v0 = c[mt][nt][rs * 2 + 0] + bias[n];
                float v1 = c[mt][nt][rs * 2 + 1] + bias[n + 1];
                float2 res;
                if (MODE == 0) {
                    res.x = interior ? fmaxf(v0, 0.f) : 0.f;
                    res.y = interior ? fmaxf(v1, 0.f) : 0.f;
                } else {
                    float2 y = *(const float2*)(g_y1 + rowoff + n);
                    res.x = y.x + (interior ? v0 : 0.f);
                    res.y = y.y + (interior ? v1 : 0.f);
                }
                *(float2*)(dst + rowoff + n) = res;
            }
        }
    }
}

// ---------------- launcher ----------------
extern "C" void kernel_launch(void* const* d_in, const int* in_sizes, int n_in,
                              void* d_out, int out_size)
{
    const float* x     = (const float*)d_in[0];
    const float* ln1_g = (const float*)d_in[1];
    const float* ln1_b = (const float*)d_in[2];
    const float* wq    = (const float*)d_in[3];
    const float* bq    = (const float*)d_in[4];
    const float* wk    = (const float*)d_in[5];
    const float* bk    = (const float*)d_in[6];
    const float* wv    = (const float*)d_in[7];
    const float* bv    = (const float*)d_in[8];
    const float* wo    = (const float*)d_in[9];
    const float* bo    = (const float*)d_in[10];
    const float* ln2_g = (const float*)d_in[11];
    const float* ln2_b = (const float*)d_in[12];
    const float* c1_w  = (const float*)d_in[13];
    const float* c1_b  = (const float*)d_in[14];
    const float* c2_w  = (const float*)d_in[15];
    const float* c2_b  = (const float*)d_in[16];
    float* outp = (float*)d_out;

    cudaFuncSetAttribute(conv_mma_kernel<0>,
                         cudaFuncAttributeMaxDynamicSharedMemorySize, CONV_SMEM_BYTES);
    cudaFuncSetAttribute(conv_mma_kernel<1>,
                         cudaFuncAttributeMaxDynamicSharedMemorySize, CONV_SMEM_BYTES);
    cudaFuncSetAttribute(qkv_mma_kernel,
                         cudaFuncAttributeMaxDynamicSharedMemorySize, QKV_SMEM_BYTES);
    cudaFuncSetAttribute(proj_mma_kernel,
                         cudaFuncAttributeMaxDynamicSharedMemorySize, PROJ_SMEM_BYTES);

    qkv_mma_kernel<<<(Bc*Lc)/64, 192, QKV_SMEM_BYTES>>>(x, ln1_g, ln1_b,
                                                        wq, bq, wk, bk, wv, bv);
    attn_kernel<<<dim3(Lc/128, Hc, Bc), 256>>>();
    proj_mma_kernel<<<(Bc*Lc)/64, 256, PROJ_SMEM_BYTES>>>(x, wo, bo, ln2_g, ln2_b);
    conv_mma_kernel<0><<<dim3(Lc/64, Bc), 256, CONV_SMEM_BYTES>>>(c1_w, c1_b, outp);
    conv_mma_kernel<1><<<dim3(Lc/64, Bc), 256, CONV_SMEM_BYTES>>>(c2_w, c2_b, outp);
}

// round 17
// speedup vs baseline: 1.0329x; 1.0329x over previous
#include <cuda_runtime.h>
#include <math.h>
#include <stdint.h>

#define Bc 16
#define Lc 2048
#define Dc 192
#define Hc 4
#define Kc 12

// ---------------- scratch (no allocations allowed) ----------------
__device__ float g_xn [(size_t)Bc*Lc*Dc];       // xn2 (written by fused proj+LN2)
__device__ float g_q  [(size_t)Bc*Hc*Lc*Kc];    // [B,H,L,K]
__device__ float g_k  [(size_t)Bc*Hc*Lc*Kc];
__device__ float g_v  [(size_t)Bc*Hc*Lc*Kc];
__device__ float g_ctx[(size_t)Bc*Lc*Hc*Kc];    // [B,L,H,K]
__device__ float g_y1 [(size_t)Bc*Lc*Dc];       // x + MHA
__device__ float g_h  [(size_t)Bc*Lc*Dc];       // relu(conv1), zero rows 0, L-1

__device__ __forceinline__ float ex2(float x) {
    float y; asm("ex2.approx.f32 %0, %1;" : "=f"(y) : "f"(x)); return y;
}
__device__ __forceinline__ float to_tf32(float x) {
    uint32_t u; asm("cvt.rna.tf32.f32 %0, %1;" : "=r"(u) : "f"(x));
    return __uint_as_float(u);
}
__device__ __forceinline__ uint32_t tf32b(float x) {
    uint32_t u; asm("cvt.rna.tf32.f32 %0, %1;" : "=r"(u) : "f"(x));
    return u;
}
__device__ __forceinline__ float4 tf32x4(float4 v) {
    return make_float4(to_tf32(v.x), to_tf32(v.y), to_tf32(v.z), to_tf32(v.w));
}
__device__ __forceinline__ void mma_tf32(float* c, const uint32_t* a,
                                         uint32_t b0, uint32_t b1)
{
    asm volatile(
        "mma.sync.aligned.m16n8k8.row.col.f32.tf32.tf32.f32 "
        "{%0,%1,%2,%3}, {%4,%5,%6,%7}, {%8,%9}, {%0,%1,%2,%3};"
        : "+f"(c[0]), "+f"(c[1]), "+f"(c[2]), "+f"(c[3])
        : "r"(a[0]), "r"(a[1]), "r"(a[2]), "r"(a[3]), "r"(b0), "r"(b1));
}

// ---------------- QKV projection + fused LN1: tf32 MMA ----------------
#define QA_S 196
#define QB_S 152
#define QA_FLOATS (64 * QA_S)
#define QB_FLOATS (32 * QB_S)
#define QKV_SMEM_BYTES ((QA_FLOATS + 2 * QB_FLOATS) * 4)

__global__ __launch_bounds__(192, 2)
void qkv_mma_kernel(const float* __restrict__ x,
                    const float* __restrict__ ln_g, const float* __restrict__ ln_b,
                    const float* __restrict__ wq, const float* __restrict__ bq,
                    const float* __restrict__ wk, const float* __restrict__ bk,
                    const float* __restrict__ wv, const float* __restrict__ bv)
{
    extern __shared__ float smem[];
    float* sA = smem;                 // [64][196]
    float* sB = smem + QA_FLOATS;     // [2][32][152]

    const int tid  = threadIdx.x;
    const int w    = tid >> 5;
    const int lane = tid & 31;
    const int tig  = lane & 3;
    const int grp  = lane >> 2;
    const int rowbase = blockIdx.x * 64;
    const int bb   = rowbase / Lc;
    const int lloc = rowbase % Lc;

    auto loadW = [&](int kc, int bf) {
        float* dstb = sB + bf * QB_FLOATS;
#pragma unroll
        for (int it = 0; it < 6; it++) {
            int idx = tid + it * 192;
            int k = idx / 36, c = (idx % 36) * 4;
            int m = c / 48, lc = c % 48;
            const float* src = (m == 0) ? wq : (m == 1) ? wk : wv;
            float4 v = *(const float4*)(src + (size_t)(kc * 32 + k) * 48 + lc);
            *(float4*)(dstb + k * QB_S + c) = tf32x4(v);
        }
    };

    for (int idx = tid; idx < 64 * 48; idx += 192) {
        int r = idx / 48, c4 = (idx % 48) * 4;
        *(float4*)(sA + r * QA_S + c4) =
            *(const float4*)(x + (size_t)(rowbase + r) * Dc + c4);
    }
    loadW(0, 0);
    __syncthreads();

    for (int r = w; r < 64; r += 6) {
        float vv[6]; float s = 0.f;
#pragma unroll
        for (int i = 0; i < 6; i++) { vv[i] = sA[r * QA_S + lane + 32*i]; s += vv[i]; }
#pragma unroll
        for (int o = 16; o; o >>= 1) s += __shfl_xor_sync(0xffffffffu, s, o);
        float mean = s * (1.f/192.f);
        float vs = 0.f;
#pragma unroll
        for (int i = 0; i < 6; i++) { float dd = vv[i] - mean; vs += dd*dd; }
#pragma unroll
        for (int o = 16; o; o >>= 1) vs += __shfl_xor_sync(0xffffffffu, vs, o);
        float inv = rsqrtf(vs * (1.f/192.f) + 1e-3f);
#pragma unroll
        for (int i = 0; i < 6; i++) {
            int c = lane + 32*i;
            sA[r * QA_S + c] = to_tf32((vv[i] - mean) * inv * ln_g[c] + ln_b[c]);
        }
    }
    __syncthreads();

    const int s     = w >> 1;
    const int mbase = (w & 1) * 32;
    float c[2][6][4];
#pragma unroll
    for (int i = 0; i < 2; i++)
#pragma unroll
        for (int j = 0; j < 6; j++)
#pragma unroll
            for (int q = 0; q < 4; q++) c[i][j][q] = 0.f;

    int buf = 0;
    for (int kc = 0; kc < 6; kc++) {
        if (kc < 5) loadW(kc + 1, buf ^ 1);
        const float* bBuf = sB + buf * QB_FLOATS + s * 48;
#pragma unroll
        for (int ks = 0; ks < 4; ks++) {
            const int c0 = kc * 32 + ks * 8;
            uint32_t a[2][4];
#pragma unroll
            for (int mt = 0; mt < 2; mt++) {
                const float* ap = sA + (mbase + mt * 16 + grp) * QA_S + c0 + tig;
                a[mt][0] = __float_as_uint(ap[0]);
                a[mt][1] = __float_as_uint(ap[8 * QA_S]);
                a[mt][2] = __float_as_uint(ap[4]);
                a[mt][3] = __float_as_uint(ap[8 * QA_S + 4]);
            }
            const float* bp = bBuf + (ks * 8 + tig) * QB_S + grp;
#pragma unroll
            for (int nt = 0; nt < 6; nt++) {
                uint32_t b0 = __float_as_uint(bp[nt * 8]);
                uint32_t b1 = __float_as_uint(bp[nt * 8 + 4 * QB_S]);
                mma_tf32(c[0][nt], a[0], b0, b1);
                mma_tf32(c[1][nt], a[1], b0, b1);
            }
        }
        __syncthreads();
        buf ^= 1;
    }

    const float* Bp = (s == 0) ? bq : (s == 1) ? bk : bv;
    float* O = (s == 0) ? g_q : (s == 1) ? g_k : g_v;
#pragma unroll
    for (int mt = 0; mt < 2; mt++) {
#pragma unroll
        for (int rs = 0; rs < 2; rs++) {
            int l = lloc + mbase + mt * 16 + grp + rs * 8;
#pragma unroll
            for (int nt = 0; nt < 6; nt++) {
                int n = nt * 8 + tig * 2;
                int h = n / 12, kk = n % 12;
                float2 res;
                res.x = c[mt][nt][rs * 2 + 0] + Bp[n];
                res.y = c[mt][nt][rs * 2 + 1] + Bp[n + 1];
                *(float2*)(O + (((size_t)bb * Hc + h) * Lc + l) * Kc + kk) = res;
            }
        }
    }
}

// ---------------- causal attention: tf32 MMA flash, 32 queries/warp ------------
// Block: 256 queries (8 warps x 2 m-tiles x 16 rows), 64-key tiles.
// K/V b-fragments shared across both m-tiles; S in nt-chunks of 4 (reg bound).
#define SK_S 20
#define SV_S 68
#define SP_S 68
#define ATTN_SK_FLOATS (64 * SK_S)
#define ATTN_SV_FLOATS (16 * SV_S)
#define ATTN_SP_FLOATS (8 * 32 * SP_S)
#define ATTN_SMEM_BYTES ((ATTN_SK_FLOATS + ATTN_SV_FLOATS + ATTN_SP_FLOATS) * 4)

__global__ __launch_bounds__(256, 2)
void attn_kernel()
{
    extern __shared__ float smem[];
    float* sK  = smem;                                  // [64][20]
    float* sVt = smem + ATTN_SK_FLOATS;                 // [16][68]
    float* sP  = smem + ATTN_SK_FLOATS + ATTN_SV_FLOATS;// [8][32][68]

    const int qt   = gridDim.x - 1 - blockIdx.x;        // heavy tiles first
    const int h    = blockIdx.y, bb = blockIdx.z;
    const int tid  = threadIdx.x;
    const int w    = tid >> 5;
    const int lane = tid & 31;
    const int grp  = lane >> 2;
    const int tig  = lane & 3;

    size_t head = ((size_t)bb * Hc + h) * Lc * Kc;
    const float* qp = g_q + head;
    const float* kp = g_k + head;
    const float* vp = g_v + head;

    // zero pad regions (published by first-tile __syncthreads)
    sK[(tid >> 2) * SK_S + 12 + (tid & 3)] = 0.f;       // 64x4
    sVt[(12 + (tid >> 6)) * SV_S + (tid & 63)] = 0.f;   // 4x64

    const int qbase = qt * 256;
    const float scale = 0.4164682333693345f;            // log2(e)/sqrt(12)

    uint32_t qa[2][2][4];
#pragma unroll
    for (int mt = 0; mt < 2; mt++) {
        int l0 = qbase + w * 32 + mt * 16 + grp;
        int l8 = l0 + 8;
        qa[mt][0][0] = tf32b(qp[(size_t)l0 * 12 + tig] * scale);
        qa[mt][0][1] = tf32b(qp[(size_t)l8 * 12 + tig] * scale);
        qa[mt][0][2] = tf32b(qp[(size_t)l0 * 12 + tig + 4] * scale);
        qa[mt][0][3] = tf32b(qp[(size_t)l8 * 12 + tig + 4] * scale);
        qa[mt][1][0] = tf32b(qp[(size_t)l0 * 12 + tig + 8] * scale);
        qa[mt][1][1] = tf32b(qp[(size_t)l8 * 12 + tig + 8] * scale);
        qa[mt][1][2] = 0u;
        qa[mt][1][3] = 0u;
    }

    float oc[2][2][4];
#pragma unroll
    for (int mt = 0; mt < 2; mt++)
#pragma unroll
        for (int i = 0; i < 2; i++)
#pragma unroll
            for (int j = 0; j < 4; j++) oc[mt][i][j] = 0.f;
    float dsum[2][2] = {{0.f, 0.f}, {0.f, 0.f}};

    const int ntile = 4 * qt + 4;
    for (int kt = 0; kt < ntile; kt++) {
        __syncthreads();
        if (tid < 192) {
            int key = tid / 3, c4 = (tid % 3) * 4;
            float4 kv = *(const float4*)(kp + (size_t)(kt * 64 + key) * 12 + c4);
            *(float4*)&sK[key * SK_S + c4] = tf32x4(kv);
            float4 vv = *(const float4*)(vp + (size_t)(kt * 64 + key) * 12 + c4);
            sVt[(c4+0) * SV_S + key] = to_tf32(vv.x);
            sVt[(c4+1) * SV_S + key] = to_tf32(vv.y);
            sVt[(c4+2) * SV_S + key] = to_tf32(vv.z);
            sVt[(c4+3) * SV_S + key] = to_tf32(vv.w);
        }
        __syncthreads();

        const bool masked = (kt >= 4 * qt);
        const int koff = (kt - 4 * qt) * 64;

        // S + softmax in nt-chunks of 4 (bounds cS registers)
#pragma unroll
        for (int ntc = 0; ntc < 8; ntc += 4) {
            float cS[2][4][4];
#pragma unroll
            for (int mt = 0; mt < 2; mt++)
#pragma unroll
                for (int nt = 0; nt < 4; nt++)
#pragma unroll
                    for (int q = 0; q < 4; q++) cS[mt][nt][q] = 0.f;
#pragma unroll
            for (int nt = 0; nt < 4; nt++) {
#pragma unroll
                for (int kc = 0; kc < 2; kc++) {
                    uint32_t b0 = __float_as_uint(sK[((ntc+nt)*8+grp)*SK_S + kc*8+tig]);
                    uint32_t b1 = __float_as_uint(sK[((ntc+nt)*8+grp)*SK_S + kc*8+tig+4]);
                    mma_tf32(cS[0][nt], qa[0][kc], b0, b1);
                    mma_tf32(cS[1][nt], qa[1][kc], b0, b1);
                }
            }
#pragma unroll
            for (int mt = 0; mt < 2; mt++) {
                const int qloc0 = w * 32 + mt * 16 + grp;
                const int qloc1 = qloc0 + 8;
#pragma unroll
                for (int nt = 0; nt < 4; nt++) {
                    int kl = (ntc + nt) * 8 + 2 * tig;
                    float p0 = ex2(cS[mt][nt][0]);
                    float p1 = ex2(cS[mt][nt][1]);
                    float p2 = ex2(cS[mt][nt][2]);
                    float p3 = ex2(cS[mt][nt][3]);
                    if (masked) {
                        if (koff + kl     > qloc0) p0 = 0.f;
                        if (koff + kl + 1 > qloc0) p1 = 0.f;
                        if (koff + kl     > qloc1) p2 = 0.f;
                        if (koff + kl + 1 > qloc1) p3 = 0.f;
                    }
                    dsum[mt][0] += p0 + p1;
                    dsum[mt][1] += p2 + p3;
                    float2 lo = make_float2(to_tf32(p0), to_tf32(p1));
                    float2 hi = make_float2(to_tf32(p2), to_tf32(p3));
                    *(float2*)&sP[(w*32 + mt*16 + grp)     * SP_S + kl] = lo;
                    *(float2*)&sP[(w*32 + mt*16 + grp + 8) * SP_S + kl] = hi;
                }
            }
        }
        __syncwarp();

        // PV: b-fragments shared across both m-tiles
#pragma unroll
        for (int kc = 0; kc < 8; kc++) {
            uint32_t b0[2], b1[2];
#pragma unroll
            for (int nt2 = 0; nt2 < 2; nt2++) {
                b0[nt2] = __float_as_uint(sVt[(nt2*8+grp)*SV_S + kc*8+tig]);
                b1[nt2] = __float_as_uint(sVt[(nt2*8+grp)*SV_S + kc*8+tig+4]);
            }
#pragma unroll
            for (int mt = 0; mt < 2; mt++) {
                uint32_t a[4];
                a[0] = __float_as_uint(sP[(w*32 + mt*16 + grp)     * SP_S + kc*8+tig]);
                a[1] = __float_as_uint(sP[(w*32 + mt*16 + grp + 8) * SP_S + kc*8+tig]);
                a[2] = __float_as_uint(sP[(w*32 + mt*16 + grp)     * SP_S + kc*8+tig+4]);
                a[3] = __float_as_uint(sP[(w*32 + mt*16 + grp + 8) * SP_S + kc*8+tig+4]);
                mma_tf32(oc[mt][0], a, b0[0], b1[0]);
                mma_tf32(oc[mt][1], a, b0[1], b1[1]);
            }
        }
    }

#pragma unroll
    for (int mt = 0; mt < 2; mt++) {
        float d0 = dsum[mt][0], d1 = dsum[mt][1];
        d0 += __shfl_xor_sync(0xffffffffu, d0, 1);
        d0 += __shfl_xor_sync(0xffffffffu, d0, 2);
        d1 += __shfl_xor_sync(0xffffffffu, d1, 1);
        d1 += __shfl_xor_sync(0xffffffffu, d1, 2);
        float i0 = 1.f / d0, i1 = 1.f / d1;
        int l0 = qbase + w * 32 + mt * 16 + grp;
        int l8 = l0 + 8;
        float* o0 = g_ctx + (((size_t)bb * Lc + l0) * Hc + h) * Kc;
        float* o1 = g_ctx + (((size_t)bb * Lc + l8) * Hc + h) * Kc;
        *(float2*)(o0 + 2 * tig) = make_float2(oc[mt][0][0] * i0, oc[mt][0][1] * i0);
        *(float2*)(o1 + 2 * tig) = make_float2(oc[mt][0][2] * i1, oc[mt][0][3] * i1);
        if (tig < 2) {
            *(float2*)(o0 + 8 + 2 * tig) = make_float2(oc[mt][1][0] * i0, oc[mt][1][1] * i0);
            *(float2*)(o1 + 8 + 2 * tig) = make_float2(oc[mt][1][2] * i1, oc[mt][1][3] * i1);
        }
    }
}

// ---------------- output projection + residual + fused LN2: tf32 MMA ----------
#define PA_S 52
#define PB_S 200
#define PA_FLOATS (64 * PA_S)
#define PB_FLOATS (48 * PB_S)
#define PST_S 196
#define PROJ_SMEM_BYTES ((PA_FLOATS + PB_FLOATS) * 4)

__global__ __launch_bounds__(256, 4)
void proj_mma_kernel(const float* __restrict__ x,
                     const float* __restrict__ wo,
                     const float* __restrict__ bo,
                     const float* __restrict__ ln_g,
                     const float* __restrict__ ln_b)
{
    extern __shared__ float smem[];
    float* sA = smem;                 // [64][52]
    float* sB = smem + PA_FLOATS;     // [48][200]

    const int tid  = threadIdx.x;
    const int w    = tid >> 5;
    const int lane = tid & 31;
    const int tig  = lane & 3;
    const int grp  = lane >> 2;
    const int rowbase = blockIdx.x * 64;

    for (int idx = tid; idx < 64 * 12; idx += 256) {
        int r = idx / 12, c4 = (idx % 12) * 4;
        float4 v = *(const float4*)(g_ctx + (size_t)(rowbase + r) * 48 + c4);
        *(float4*)(sA + r * PA_S + c4) = tf32x4(v);
    }
    for (int idx = tid; idx < 48 * 48; idx += 256) {
        int r = idx / 48, c4 = (idx % 48) * 4;
        float4 v = *(const float4*)(wo + (size_t)r * Dc + c4);
        *(float4*)(sB + r * PB_S + c4) = tf32x4(v);
    }
    __syncthreads();

    const int mbase = (w & 1) * 32;
    const int nbase = (w >> 1) * 48;
    float c[2][6][4];
#pragma unroll
    for (int i = 0; i < 2; i++)
#pragma unroll
        for (int j = 0; j < 6; j++)
#pragma unroll
            for (int q = 0; q < 4; q++) c[i][j][q] = 0.f;

#pragma unroll
    for (int ks = 0; ks < 6; ks++) {
        const int c0 = ks * 8;
        uint32_t a[2][4];
#pragma unroll
        for (int mt = 0; mt < 2; mt++) {
            const float* ap = sA + (mbase + mt * 16 + grp) * PA_S + c0 + tig;
            a[mt][0] = __float_as_uint(ap[0]);
            a[mt][1] = __float_as_uint(ap[8 * PA_S]);
            a[mt][2] = __float_as_uint(ap[4]);
            a[mt][3] = __float_as_uint(ap[8 * PA_S + 4]);
        }
        const float* bp = sB + (c0 + tig) * PB_S + nbase + grp;
#pragma unroll
        for (int nt = 0; nt < 6; nt++) {
            uint32_t b0 = __float_as_uint(bp[nt * 8]);
            uint32_t b1 = __float_as_uint(bp[nt * 8 + 4 * PB_S]);
            mma_tf32(c[0][nt], a[0], b0, b1);
            mma_tf32(c[1][nt], a[1], b0, b1);
        }
    }
    __syncthreads();                       // done with sA/sB; reuse as stage

    float* stage = smem;                   // [64][196]
#pragma unroll
    for (int mt = 0; mt < 2; mt++) {
#pragma unroll
        for (int rs = 0; rs < 2; rs++) {
            int r = mbase + mt * 16 + grp + rs * 8;
            size_t off = (size_t)(rowbase + r) * Dc;
#pragma unroll
            for (int nt = 0; nt < 6; nt++) {
                int n = nbase + nt * 8 + tig * 2;
                float2 xv = *(const float2*)(x + off + n);
                float2 res;
                res.x = c[mt][nt][rs * 2 + 0] + bo[n]     + xv.x;
                res.y = c[mt][nt][rs * 2 + 1] + bo[n + 1] + xv.y;
                *(float2*)(g_y1 + off + n) = res;
                *(float2*)(stage + r * PST_S + n) = res;
            }
        }
    }
    __syncthreads();

    for (int r = w; r < 64; r += 8) {
        float vv[6]; float s = 0.f;
#pragma unroll
        for (int i = 0; i < 6; i++) { vv[i] = stage[r * PST_S + lane + 32*i]; s += vv[i]; }
#pragma unroll
        for (int o = 16; o; o >>= 1) s += __shfl_xor_sync(0xffffffffu, s, o);
        float mean = s * (1.f/192.f);
        float vs = 0.f;
#pragma unroll
        for (int i = 0; i < 6; i++) { float dd = vv[i] - mean; vs += dd*dd; }
#pragma unroll
        for (int o = 16; o; o >>= 1) vs += __shfl_xor_sync(0xffffffffu, vs, o);
        float inv = rsqrtf(vs * (1.f/192.f) + 1e-3f);
#pragma unroll
        for (int i = 0; i < 6; i++) {
            int cc = lane + 32*i;
            g_xn[(size_t)(rowbase + r) * Dc + cc] =
                (vv[i] - mean) * inv * ln_g[cc] + ln_b[cc];
        }
    }
}

// ---------------- conv1d as tf32 tensor-core GEMM (R15 proven) ----------------
#define SA_STRIDE 196
#define SB_STRIDE 200
#define SA_FLOATS (66 * SA_STRIDE)
#define SB_FLOATS (32 * SB_STRIDE)
#define CONV_SMEM_BYTES ((SA_FLOATS + 2 * SB_FLOATS) * 4)

template<int MODE>
__global__ __launch_bounds__(256, 2)
void conv_mma_kernel(const float* __restrict__ W,
                     const float* __restrict__ bias,
                     float* __restrict__ out)
{
    extern __shared__ float smem[];
    float* sA = smem;                    // [66][196]
    float* sB = smem + SA_FLOATS;        // [2][32][200]

    const int tid  = threadIdx.x;
    const int w    = tid >> 5;
    const int lane = tid & 31;
    const int tig  = lane & 3;
    const int grp  = lane >> 2;
    const int l0   = blockIdx.x * 64;
    const int bb   = blockIdx.y;
    const float* srcb = ((MODE == 0) ? g_xn : g_h) + (size_t)bb * Lc * Dc;

    for (int idx = tid; idx < 66 * 48; idx += 256) {
        int r = idx / 48, c4 = (idx % 48) * 4;
        int l = l0 - 1 + r; l = l < 0 ? 0 : (l > Lc - 1 ? Lc - 1 : l);
        float4 v = *(const float4*)(srcb + (size_t)l * Dc + c4);
        *(float4*)(sA + r * SA_STRIDE + c4) = tf32x4(v);
    }

    const int mbase = (w & 1) * 32;
    const int nbase = (w >> 1) * 48;
    float c[2][6][4];
#pragma unroll
    for (int i = 0; i < 2; i++)
#pragma unroll
        for (int j = 0; j < 6; j++)
#pragma unroll
            for (int q = 0; q < 4; q++) c[i][j][q] = 0.f;

    auto loadW = [&](int kc, int bf) {
        float* dstb = sB + bf * SB_FLOATS;
#pragma unroll
        for (int it = 0; it < 6; it++) {
            int idx = tid + it * 256;
            int k = idx / 48, c4 = (idx % 48) * 4;
            float4 v = *(const float4*)(W + ((size_t)(kc * 32 + k)) * Dc + c4);
            *(float4*)(dstb + k * SB_STRIDE + c4) = tf32x4(v);
        }
    };

    loadW(0, 0);
    __syncthreads();

    int buf = 0;
    for (int kc = 0; kc < 18; kc++) {
        if (kc < 17) loadW(kc + 1, buf ^ 1);
        const int t  = kc / 6;
        const int cc = (kc % 6) * 32;
        const float* bBuf = sB + buf * SB_FLOATS;
#pragma unroll
        for (int ks = 0; ks < 4; ks++) {
            const int c0 = cc + ks * 8;
            uint32_t a[2][4];
#pragma unroll
            for (int mt = 0; mt < 2; mt++) {
                const float* ap = sA + (mbase + mt * 16 + grp + t) * SA_STRIDE + c0 + tig;
                a[mt][0] = __float_as_uint(ap[0]);
                a[mt][1] = __float_as_uint(ap[8 * SA_STRIDE]);
                a[mt][2] = __float_as_uint(ap[4]);
                a[mt][3] = __float_as_uint(ap[8 * SA_STRIDE + 4]);
            }
            const float* bp = bBuf + (ks * 8 + tig) * SB_STRIDE + nbase + grp;
#pragma unroll
            for (int nt = 0; nt < 6; nt++) {
                uint32_t b0 = __float_as_uint(bp[nt * 8]);
                uint32_t b1 = __float_as_uint(bp[nt * 8 + 4 * SB_STRIDE]);
                mma_tf32(c[0][nt], a[0], b0, b1);
                mma_tf32(c[1][nt], a[1], b0, b1);
            }
        }
        __syncthreads();
        buf ^= 1;
    }

    float* dst = (MODE == 0) ? g_h : out;
#pragma unroll
    for (int mt = 0; mt < 2; mt++) {
#pragma unroll
        for (int rs = 0; rs < 2; rs++) {
            int l = l0 + mbase + mt * 16 + grp + rs * 8;
            bool interior = (l >= 1) && (l <= Lc - 2);
            size_t rowoff = ((size_t)bb * Lc + l) * Dc;
#pragma unroll
            for (int nt = 0; nt < 6; nt++) {
                int n = nbase + nt * 8 + tig * 2;
                float v0 = c[mt][nt][rs * 2 + 0] + bias[n];
                float v1 = c[mt][nt][rs * 2 + 1] + bias[n + 1];
                float2 res;
                if (MODE == 0) {
                    res.x = interior ? fmaxf(v0, 0.f) : 0.f;
                    res.y = interior ? fmaxf(v1, 0.f) : 0.f;
                } else {
                    float2 y = *(const float2*)(g_y1 + rowoff + n);
                    res.x = y.x + (interior ? v0 : 0.f);
                    res.y = y.y + (interior ? v1 : 0.f);
                }
                *(float2*)(dst + rowoff + n) = res;
            }
        }
    }
}

// ---------------- launcher ----------------
extern "C" void kernel_launch(void* const* d_in, const int* in_sizes, int n_in,
                              void* d_out, int out_size)
{
    const float* x     = (const float*)d_in[0];
    const float* ln1_g = (const float*)d_in[1];
    const float* ln1_b = (const float*)d_in[2];
    const float* wq    = (const float*)d_in[3];
    const float* bq    = (const float*)d_in[4];
    const float* wk    = (const float*)d_in[5];
    const float* bk    = (const float*)d_in[6];
    const float* wv    = (const float*)d_in[7];
    const float* bv    = (const float*)d_in[8];
    const float* wo    = (const float*)d_in[9];
    const float* bo    = (const float*)d_in[10];
    const float* ln2_g = (const float*)d_in[11];
    const float* ln2_b = (const float*)d_in[12];
    const float* c1_w  = (const float*)d_in[13];
    const float* c1_b  = (const float*)d_in[14];
    const float* c2_w  = (const float*)d_in[15];
    const float* c2_b  = (const float*)d_in[16];
    float* outp = (float*)d_out;

    cudaFuncSetAttribute(conv_mma_kernel<0>,
                         cudaFuncAttributeMaxDynamicSharedMemorySize, CONV_SMEM_BYTES);
    cudaFuncSetAttribute(conv_mma_kernel<1>,
                         cudaFuncAttributeMaxDynamicSharedMemorySize, CONV_SMEM_BYTES);
    cudaFuncSetAttribute(qkv_mma_kernel,
                         cudaFuncAttributeMaxDynamicSharedMemorySize, QKV_SMEM_BYTES);
    cudaFuncSetAttribute(proj_mma_kernel,
                         cudaFuncAttributeMaxDynamicSharedMemorySize, PROJ_SMEM_BYTES);
    cudaFuncSetAttribute(attn_kernel,
                         cudaFuncAttributeMaxDynamicSharedMemorySize, ATTN_SMEM_BYTES);

    qkv_mma_kernel<<<(Bc*Lc)/64, 192, QKV_SMEM_BYTES>>>(x, ln1_g, ln1_b,
                                                        wq, bq, wk, bk, wv, bv);
    attn_kernel<<<dim3(Lc/256, Hc, Bc), 256, ATTN_SMEM_BYTES>>>();
    proj_mma_kernel<<<(Bc*Lc)/64, 256, PROJ_SMEM_BYTES>>>(x, wo, bo, ln2_g, ln2_b);
    conv_mma_kernel<0><<<dim3(Lc/64, Bc), 256, CONV_SMEM_BYTES>>>(c1_w, c1_b, outp);
    conv_mma_kernel<1><<<dim3(Lc/64, Bc), 256, CONV_SMEM_BYTES>>>(c2_w, c2_b, outp);
}